// round 10
// baseline (speedup 1.0000x reference)
#include <cuda_runtime.h>
#include <cuda_fp16.h>
#include <mma.h>
#include <math.h>
#include <stdint.h>

using namespace nvcuda;

// Problem constants
#define BT   32768
#define DIN  768
#define DH   384
#define DH2  192
#define DOUT 256
#define NE   5
#define DELTA 0.35f

// ---- tf32 split GEMM config (recheck path) ----
#define LDS_PAD 20
#define TSTAGE_FLOATS 5120
#define TSTAGE_BYTES  20480
#define TBOFF_BYTES   10240
#define TSMEM (4 * TSTAGE_BYTES)

// ---------------- scratch (device globals) ----------------
__device__ float  g_bufB[(size_t)BT * DH2];
__device__ float  g_Y[(size_t)BT * DOUT];
__device__ float  g_fA[(size_t)BT * DH];
__device__ float  g_fB[(size_t)BT * DH2];
__device__ float  g_bc[NE * DOUT];
__device__ __half g_t16a[(size_t)BT * DH];
__device__ __half g_t16b[(size_t)BT * DH];
__device__ __half g_y16[(size_t)BT * DOUT];
__device__ __half g_wch[(size_t)NE * DOUT * DOUT];
__device__ __half g_rw1h[DH * DIN];
__device__ __half g_rw2h[DH2 * DH];
__device__ __half g_ew1h[(size_t)NE * DH * DIN];
__device__ __half g_ew2h[(size_t)NE * DH * DH];
__device__ __half g_ew3h[(size_t)NE * DOUT * DH];
__device__ int    g_eidx[BT];
__device__ int    g_perm[BT];
__device__ int    g_cnt[NE];
__device__ int    g_off[NE + 1];
__device__ int    g_cur[NE];
__device__ int    g_flag[BT];
__device__ int    g_nflag;
__device__ int    g_nseg[2];

__device__ __forceinline__ float tf32r(float x) { return wmma::__float_to_tf32(x); }

__device__ __forceinline__ uint32_t smem_u32(const void* p) {
    uint32_t a;
    asm("{ .reg .u64 t; cvta.to.shared.u64 t, %1; cvt.u32.u64 %0, t; }" : "=r"(a) : "l"(p));
    return a;
}
__device__ __forceinline__ void cpasync16(uint32_t dst, const void* src) {
    asm volatile("{ .reg .u64 g; cvta.to.global.u64 g, %1;"
                 "cp.async.ca.shared.global [%0], [g], 16; }"
                 :: "r"(dst), "l"(src) : "memory");
}
__device__ __forceinline__ void sts_half8(uint32_t addr, float4 u, float4 v) {
    __half2 h0 = __floats2half2_rn(u.x, u.y);
    __half2 h1 = __floats2half2_rn(u.z, u.w);
    __half2 h2 = __floats2half2_rn(v.x, v.y);
    __half2 h3 = __floats2half2_rn(v.z, v.w);
    uint32_t r0 = *(uint32_t*)&h0, r1 = *(uint32_t*)&h1;
    uint32_t r2 = *(uint32_t*)&h2, r3 = *(uint32_t*)&h3;
    asm volatile("st.shared.v4.b32 [%0], {%1,%2,%3,%4};"
                 :: "r"(addr), "r"(r0), "r"(r1), "r"(r2), "r"(r3) : "memory");
}
#define CP_COMMIT() asm volatile("cp.async.commit_group;" ::: "memory")
#define CP_WAIT1()  asm volatile("cp.async.wait_group 1;" ::: "memory")
#define CP_WAIT2()  asm volatile("cp.async.wait_group 2;" ::: "memory")
#define CP_WAIT0()  asm volatile("cp.async.wait_group 0;" ::: "memory")

// ============ fused fp16 GEMM + bias + LayerNorm epilogue (round-8 config) =======
// Block: BM=64 rows x BN=N cols (full row), 256 threads, 3-stage cp.async.
// AFP32=1: A is fp32 in gmem; loader converts to fp16 in-flight (register-staged).
// MODE 0: LN+ReLU -> fp16    MODE 1: LN+ReLU -> fp32
// MODE 2: LN -> fp16+fp32    MODE 3: +Y residual, LN, scatter fp32 via perm
template<int BN, int WM, int WN, int MODE, int AFP32>
__global__ void __launch_bounds__(256, 1)
gemm_f(const float* __restrict__ A32, const __half* __restrict__ A16,
       const int* __restrict__ gather,
       const __half* __restrict__ W, const float* __restrict__ bias,
       const float* __restrict__ lng, const float* __restrict__ lnb,
       float* __restrict__ out32, __half* __restrict__ out16,
       const float* __restrict__ addY, const int* __restrict__ permArr,
       int K, const int* __restrict__ seg, long wstride, int bstride,
       int lnstride, int Mtot)
{
    constexpr int CH = (64 + BN) / 64;     // 16B chunks per thread per stage
    constexpr int MF = 64 / WM / 16;
    constexpr int NF = BN / WN / 16;
    constexpr int STAGE_B = (64 + BN) * 80;
    constexpr int SLD = BN + 4;
    constexpr int NW = BN / 32;

    extern __shared__ char smraw[];

    int e = 0, rowbase = 0, segM = Mtot;
    if (seg) { e = blockIdx.z; rowbase = seg[e]; segM = seg[e + 1] - rowbase; }
    int mt = blockIdx.x * 64;
    if (mt >= segM) return;

    const __half* Wp = W + (long)e * wstride;
    const float*  bp = bias + (long)e * bstride;

    int tid  = threadIdx.x;
    int wid  = tid >> 5;
    int lane = tid & 31;
    int wm = (WM == 1) ? 0 : (wid / WN);
    int wn = (WM == 1) ? wid : (wid % WN);

    // loader geometry: chunk 0 = A row; chunks 1..CH-1 = B rows
    int ra = tid >> 2;
    int c8 = (tid & 3) * 8;
    int mr = mt + ra; if (mr > segM - 1) mr = segM - 1;
    int ar = gather ? gather[rowbase + mr] : rowbase + mr;
    const __half* gp[CH];
    const float* ap32 = nullptr;
    uint32_t so[CH];
    if (AFP32) ap32 = A32 + (size_t)ar * K + c8;
    else       gp[0] = A16 + (size_t)ar * K + c8;
    so[0] = (uint32_t)(ra * 40 + c8) * 2;
    #pragma unroll
    for (int i = 1; i < CH; i++) {
        int rb = ra + (i - 1) * 64;
        gp[i] = Wp + (size_t)rb * K + c8;
        so[i] = (uint32_t)(5120 + (rb * 40 + c8) * 2);
    }

    uint32_t smb = smem_u32(smraw);
    int nk = K / 32;

    auto issue = [&](int stage, int kb) {
        uint32_t base = smb + (uint32_t)stage * STAGE_B;
        int k = kb * 32;
        #pragma unroll
        for (int i = AFP32 ? 1 : 0; i < CH; i++)
            cpasync16(base + so[i], gp[i] + k);
    };

    wmma::fragment<wmma::accumulator, 16, 16, 16, float> acc[MF][NF];
    #pragma unroll
    for (int mi = 0; mi < MF; mi++)
        #pragma unroll
        for (int ni = 0; ni < NF; ni++) wmma::fill_fragment(acc[mi][ni], 0.f);

    float4 paU[2], paV[2];
    if (AFP32) {
        paU[0] = *(const float4*)(ap32);
        paV[0] = *(const float4*)(ap32 + 4);
        if (nk > 1) {
            paU[1] = *(const float4*)(ap32 + 32);
            paV[1] = *(const float4*)(ap32 + 36);
        }
    }
    issue(0, 0); CP_COMMIT();
    issue(1, 1); CP_COMMIT();
    if (AFP32) sts_half8(smb + so[0], paU[0], paV[0]);   // stage0 A

    for (int kb = 0; kb < nk; kb++) {
        float4 tU, tV;
        if (AFP32 && kb + 2 < nk) {
            tU = *(const float4*)(ap32 + (kb + 2) * 32);
            tV = *(const float4*)(ap32 + (kb + 2) * 32 + 4);
        }
        CP_WAIT1();
        __syncthreads();
        const __half* sa = (const __half*)(smraw + (kb % 3) * STAGE_B);
        const __half* sb = sa + 2560;

        #pragma unroll
        for (int ks = 0; ks < 2; ks++) {
            wmma::fragment<wmma::matrix_a, 16, 16, 16, __half, wmma::row_major> a[MF];
            wmma::fragment<wmma::matrix_b, 16, 16, 16, __half, wmma::col_major> b[NF];
            #pragma unroll
            for (int mi = 0; mi < MF; mi++)
                wmma::load_matrix_sync(a[mi], sa + (wm * (64 / WM) + mi * 16) * 40 + ks * 16, 40);
            #pragma unroll
            for (int ni = 0; ni < NF; ni++)
                wmma::load_matrix_sync(b[ni], sb + (wn * (BN / WN) + ni * 16) * 40 + ks * 16, 40);
            #pragma unroll
            for (int mi = 0; mi < MF; mi++)
                #pragma unroll
                for (int ni = 0; ni < NF; ni++)
                    wmma::mma_sync(acc[mi][ni], a[mi], b[ni], acc[mi][ni]);
        }

        if (AFP32) {
            if (kb + 1 < nk)
                sts_half8(smb + ((kb + 1) % 3) * STAGE_B + so[0],
                          paU[(kb + 1) & 1], paV[(kb + 1) & 1]);
            if (kb + 2 < nk) { paU[kb & 1] = tU; paV[kb & 1] = tV; }
        }
        int nkb = kb + 2;
        if (nkb < nk) issue(nkb % 3, nkb);
        CP_COMMIT();
    }

    // ---- epilogue: stage full 64 x BN tile, bias + LN (+relu/residual), write ----
    CP_WAIT0();
    __syncthreads();
    float* stg = (float*)smraw;
    #pragma unroll
    for (int mi = 0; mi < MF; mi++)
        #pragma unroll
        for (int ni = 0; ni < NF; ni++)
            wmma::store_matrix_sync(stg + (wm * (64 / WM) + mi * 16) * SLD + wn * (BN / WN) + ni * 16,
                                    acc[mi][ni], SLD, wmma::mem_row_major);
    __syncthreads();

    const float* gpp = lng + (long)e * lnstride;
    const float* bpp = lnb + (long)e * lnstride;

    #pragma unroll
    for (int j = 0; j < 8; j++) {
        int r = wid * 8 + j;
        int m = mt + r;
        if (m >= segM) continue;   // r uniform per warp: no shuffle divergence
        const float* srow = stg + r * SLD;

        float v[NW];
        float s = 0.f;
        #pragma unroll
        for (int i = 0; i < NW; i++) {
            int c = lane + i * 32;
            float valf = srow[c] + bp[c];
            if (MODE == 3) valf += addY[(size_t)(rowbase + m) * BN + c];
            v[i] = valf; s += valf;
        }
        #pragma unroll
        for (int o = 16; o; o >>= 1) s += __shfl_xor_sync(0xffffffffu, s, o);
        float mu = s / (float)BN;
        float sq = 0.f;
        #pragma unroll
        for (int i = 0; i < NW; i++) { float d = v[i] - mu; sq += d * d; }
        #pragma unroll
        for (int o = 16; o; o >>= 1) sq += __shfl_xor_sync(0xffffffffu, sq, o);
        float inv = 1.0f / sqrtf(sq / (float)BN + 1e-5f);

        size_t orow = (MODE == 3) ? (size_t)permArr[rowbase + m] : (size_t)(rowbase + m);
        #pragma unroll
        for (int i = 0; i < NW; i++) {
            int c = lane + i * 32;
            float o2 = (v[i] - mu) * inv * gpp[c] + bpp[c];
            if (MODE <= 1) o2 = fmaxf(o2, 0.f);
            if (MODE != 0) out32[orow * BN + c] = o2;
            if (MODE == 0 || MODE == 2) out16[orow * BN + c] = __float2half_rn(o2);
        }
    }
}

// ============ split-tf32 GEMM (~2^-24) — exact recheck path only ==================
__global__ void __launch_bounds__(256, 1)
gemm_split(const float* __restrict__ A, const int* __restrict__ gather,
           const float* __restrict__ W, const float* __restrict__ bias,
           float* __restrict__ C, int N, int K,
           const int* __restrict__ seg, int Mtot)
{
    extern __shared__ float tsm[];

    int rowbase = 0, segM = Mtot;
    if (seg) { rowbase = seg[0]; segM = seg[1] - rowbase; }
    int mt = blockIdx.x * 128;
    if (mt >= segM) return;

    const float* bp = bias;
    int n0 = blockIdx.y * 128;

    int tid = threadIdx.x;
    int wid = tid >> 5;
    int wm  = wid >> 1;
    int wn  = wid & 1;

    int rA0 = tid >> 2,         cA0 = (tid & 3) * 4;
    int rA1 = (tid + 256) >> 2;
    int mr0 = mt + rA0; if (mr0 > segM - 1) mr0 = segM - 1;
    int mr1 = mt + rA1; if (mr1 > segM - 1) mr1 = segM - 1;
    int ar0 = gather ? gather[rowbase + mr0] : rowbase + mr0;
    int ar1 = gather ? gather[rowbase + mr1] : rowbase + mr1;
    const float* ap0 = A + (size_t)ar0 * K + cA0;
    const float* ap1 = A + (size_t)ar1 * K + cA0;
    int nr0 = n0 + rA0; if (nr0 > N - 1) nr0 = N - 1;
    int nr1 = n0 + rA1; if (nr1 > N - 1) nr1 = N - 1;
    const float* bpt0 = W + (size_t)nr0 * K + cA0;
    const float* bpt1 = W + (size_t)nr1 * K + cA0;

    uint32_t smb = smem_u32(tsm);
    uint32_t offA0 = (uint32_t)(rA0 * LDS_PAD + cA0) * 4;
    uint32_t offA1 = (uint32_t)(rA1 * LDS_PAD + cA0) * 4;

    int nk = K / 16;

    auto issue = [&](int stage, int kb) {
        int k = kb * 16;
        uint32_t base = smb + stage * TSTAGE_BYTES;
        cpasync16(base + offA0, ap0 + k);
        cpasync16(base + offA1, ap1 + k);
        cpasync16(base + TBOFF_BYTES + offA0, bpt0 + k);
        cpasync16(base + TBOFF_BYTES + offA1, bpt1 + k);
    };

    wmma::fragment<wmma::accumulator, 16, 16, 8, float> acc[2][4];
    #pragma unroll
    for (int mi = 0; mi < 2; mi++)
        #pragma unroll
        for (int ni = 0; ni < 4; ni++) wmma::fill_fragment(acc[mi][ni], 0.f);

    issue(0, 0); CP_COMMIT();
    issue(1, 1); CP_COMMIT();
    issue(2, 2); CP_COMMIT();

    for (int kb = 0; kb < nk; kb++) {
        CP_WAIT2();
        __syncthreads();
        int st = kb & 3;
        const float* sa = tsm + st * TSTAGE_FLOATS;
        const float* sb = sa + 2560;

        #pragma unroll
        for (int ks = 0; ks < 2; ks++) {
            wmma::fragment<wmma::matrix_a, 16, 16, 8, wmma::precision::tf32, wmma::row_major> a[2], ah[2];
            wmma::fragment<wmma::matrix_b, 16, 16, 8, wmma::precision::tf32, wmma::col_major> b[4], bh[4];
            #pragma unroll
            for (int mi = 0; mi < 2; mi++)
                wmma::load_matrix_sync(a[mi], sa + (wm * 32 + mi * 16) * LDS_PAD + ks * 8, LDS_PAD);
            #pragma unroll
            for (int ni = 0; ni < 4; ni++)
                wmma::load_matrix_sync(b[ni], sb + (wn * 64 + ni * 16) * LDS_PAD + ks * 8, LDS_PAD);
            #pragma unroll
            for (int mi = 0; mi < 2; mi++)
                #pragma unroll
                for (int i = 0; i < a[mi].num_elements; i++) {
                    float h = tf32r(a[mi].x[i]);
                    ah[mi].x[i] = h;
                    a[mi].x[i] = tf32r(a[mi].x[i] - h);
                }
            #pragma unroll
            for (int ni = 0; ni < 4; ni++)
                #pragma unroll
                for (int i = 0; i < b[ni].num_elements; i++) {
                    float h = tf32r(b[ni].x[i]);
                    bh[ni].x[i] = h;
                    b[ni].x[i] = tf32r(b[ni].x[i] - h);
                }
            #pragma unroll
            for (int mi = 0; mi < 2; mi++)
                #pragma unroll
                for (int ni = 0; ni < 4; ni++) {
                    wmma::mma_sync(acc[mi][ni], ah[mi], bh[ni], acc[mi][ni]);
                    wmma::mma_sync(acc[mi][ni], ah[mi], b[ni],  acc[mi][ni]);
                    wmma::mma_sync(acc[mi][ni], a[mi],  bh[ni], acc[mi][ni]);
                }
        }

        int nkb = kb + 3;
        if (nkb < nk) issue(nkb & 3, nkb);
        CP_COMMIT();
    }

    CP_WAIT0();
    __syncthreads();
    float* stage = tsm;
    const int SLD = 132;
    #pragma unroll
    for (int r = 0; r < 2; r++) {
        if ((wm >> 1) == r) {
            #pragma unroll
            for (int mi = 0; mi < 2; mi++)
                #pragma unroll
                for (int ni = 0; ni < 4; ni++)
                    wmma::store_matrix_sync(stage + ((wm & 1) * 32 + mi * 16) * SLD + wn * 64 + ni * 16,
                                            acc[mi][ni], SLD, wmma::mem_row_major);
        }
        __syncthreads();
        #pragma unroll
        for (int it = 0; it < 8; it++) {
            int fidx = tid + it * 256;
            int lrow = fidx >> 5;
            int c4 = (fidx & 31) * 4;
            int m = mt + r * 64 + lrow;
            int n = n0 + c4;
            if (m < segM && n < N) {
                float4 v = *(float4*)(stage + lrow * SLD + c4);
                float4 bv = *(const float4*)(bp + n);
                v.x += bv.x; v.y += bv.y; v.z += bv.z; v.w += bv.w;
                *(float4*)(C + (size_t)(rowbase + m) * N + n) = v;
            }
        }
        __syncthreads();
    }
}

// ---------------- all weight fp32 -> fp16 conversions in ONE kernel ---------------
#define CN1 (DH * DIN / 4)
#define CN2 (DH2 * DH / 4)
#define CN3 (NE * DH * DIN / 4)
#define CN4 (NE * DH * DH / 4)
#define CN5 (NE * DOUT * DH / 4)
#define CTOT (CN1 + CN2 + CN3 + CN4 + CN5)

__global__ void cvt16_all(const float* s1, __half* d1, const float* s2, __half* d2,
                          const float* s3, __half* d3, const float* s4, __half* d4,
                          const float* s5, __half* d5)
{
    int i = blockIdx.x * blockDim.x + threadIdx.x;
    if (i >= CTOT) return;
    const float* s; __half* d; int o = i;
    if (o < CN1) { s = s1; d = d1; }
    else if ((o -= CN1) < CN2) { s = s2; d = d2; }
    else if ((o -= CN2) < CN3) { s = s3; d = d3; }
    else if ((o -= CN3) < CN4) { s = s4; d = d4; }
    else { o -= CN4; s = s5; d = d5; }
    float4 v = *(const float4*)(s + (size_t)o * 4);
    *(__half2*)(d + (size_t)o * 4)     = __floats2half2_rn(v.x, v.y);
    *(__half2*)(d + (size_t)o * 4 + 2) = __floats2half2_rn(v.z, v.w);
}

// ---------------- fuse wo @ wv (fp16 weights out) ---------------------------------
__global__ void fuse_wo_wv(const float* __restrict__ wqkv, const float* __restrict__ bqkv,
                           const float* __restrict__ wo, const float* __restrict__ bo,
                           __half* __restrict__ wch, float* __restrict__ bc)
{
    int e = blockIdx.z, n = blockIdx.y, k = threadIdx.x;
    const float* woR = wo + ((size_t)e * DOUT + n) * DOUT;
    const float* wv  = wqkv + (size_t)e * 3 * DOUT * DOUT + 2 * DOUT * DOUT;
    const float* bv  = bqkv + (size_t)e * 3 * DOUT + 2 * DOUT;
    float s = 0.f;
    for (int j = 0; j < DOUT; j++) s = fmaf(woR[j], wv[(size_t)j * DOUT + k], s);
    wch[((size_t)e * DOUT + n) * DOUT + k] = __float2half_rn(s);
    if (k == 0) {
        float sb = bo[e * DOUT + n];
        for (int j = 0; j < DOUT; j++) sb = fmaf(woR[j], bv[j], sb);
        bc[e * DOUT + n] = sb;
    }
}

// ---------------- row LayerNorm + ReLU, fp32 (recheck path only) -----------------
__global__ void ln_rows(const float* __restrict__ in, float* __restrict__ out, int Ncols,
                        const float* __restrict__ g, const float* __restrict__ b,
                        const int* __restrict__ Mdev)
{
    int row = blockIdx.x * 8 + (threadIdx.x >> 5);
    if (row >= *Mdev) return;
    int lane = threadIdx.x & 31;
    const float* ip = in + (size_t)row * Ncols;
    int nw = Ncols >> 5;

    float v[12];
    float s = 0.f;
    for (int i = 0; i < nw; i++) { v[i] = ip[lane + i * 32]; s += v[i]; }
    #pragma unroll
    for (int o = 16; o; o >>= 1) s += __shfl_xor_sync(0xffffffffu, s, o);
    float mu = s / (float)Ncols;
    float sq = 0.f;
    for (int i = 0; i < nw; i++) { float d = v[i] - mu; sq += d * d; }
    #pragma unroll
    for (int o = 16; o; o >>= 1) sq += __shfl_xor_sync(0xffffffffu, sq, o);
    float inv = 1.0f / sqrtf(sq / (float)Ncols + 1e-5f);

    float* op = out + (size_t)row * Ncols;
    for (int i = 0; i < nw; i++) {
        int c = lane + i * 32;
        op[c] = fmaxf((v[i] - mu) * inv * g[c] + b[c], 0.f);
    }
}

// ---------------- router head: provisional + ambiguity flagging -------------------
__global__ void routing_kernel(const float* __restrict__ h2, const float* __restrict__ rw3,
                               const float* __restrict__ rb3, const float* __restrict__ gumbel,
                               float* __restrict__ outRW, float* __restrict__ outIdx)
{
    int tok = blockIdx.x * 8 + (threadIdx.x >> 5);
    if (tok >= BT) return;
    int lane = threadIdx.x & 31;
    const float* h = h2 + (size_t)tok * DH2;

    float acc[NE];
    #pragma unroll
    for (int j = 0; j < NE; j++) acc[j] = 0.f;
    #pragma unroll
    for (int i = 0; i < DH2 / 32; i++) {
        int k = lane + i * 32;
        float hv = h[k];
        #pragma unroll
        for (int j = 0; j < NE; j++)
            acc[j] = fmaf(hv, rw3[j * DH2 + k], acc[j]);
    }
    #pragma unroll
    for (int j = 0; j < NE; j++)
        #pragma unroll
        for (int o = 16; o; o >>= 1)
            acc[j] += __shfl_xor_sync(0xffffffffu, acc[j], o);

    if (lane == 0) {
        float z[NE];
        float best = -1e30f, second = -1e30f; int bi = 0;
        #pragma unroll
        for (int j = 0; j < NE; j++) {
            float lg = acc[j] + rb3[j];
            z[j] = (lg + gumbel[(size_t)tok * NE + j]) / 0.07f;
            if (z[j] > best) { second = best; best = z[j]; bi = j; }
            else if (z[j] > second) second = z[j];
        }
        float ex[NE], sum = 0.f;
        #pragma unroll
        for (int j = 0; j < NE; j++) { ex[j] = expf(z[j] - best); sum += ex[j]; }
        #pragma unroll
        for (int j = 0; j < NE; j++) {
            float ys = ex[j] / sum;
            float hard = (j == bi) ? 1.f : 0.f;
            outRW[(size_t)tok * NE + j] = (hard + ys) - ys;
        }
        outIdx[tok] = (float)bi;
        g_eidx[tok] = bi;
        atomicAdd(&g_cnt[bi], 1);
        if (best - second < DELTA) {
            int p = atomicAdd(&g_nflag, 1);
            g_flag[p] = tok;
        }
    }
}

__global__ void set_nseg()
{
    if (threadIdx.x == 0) { g_nseg[0] = 0; g_nseg[1] = g_nflag; }
}

// ---------------- exact routing fix for flagged tokens ---------------------------
__global__ void routing_fix(const float* __restrict__ h2f, const float* __restrict__ rw3,
                            const float* __restrict__ rb3, const float* __restrict__ gumbel,
                            float* __restrict__ outRW, float* __restrict__ outIdx)
{
    int fi = blockIdx.x * 8 + (threadIdx.x >> 5);
    if (fi >= g_nflag) return;
    int lane = threadIdx.x & 31;
    int tok = g_flag[fi];
    const float* h = h2f + (size_t)fi * DH2;

    float acc[NE];
    #pragma unroll
    for (int j = 0; j < NE; j++) acc[j] = 0.f;
    #pragma unroll
    for (int i = 0; i < DH2 / 32; i++) {
        int k = lane + i * 32;
        float hv = h[k];
        #pragma unroll
        for (int j = 0; j < NE; j++)
            acc[j] = fmaf(hv, rw3[j * DH2 + k], acc[j]);
    }
    #pragma unroll
    for (int j = 0; j < NE; j++)
        #pragma unroll
        for (int o = 16; o; o >>= 1)
            acc[j] += __shfl_xor_sync(0xffffffffu, acc[j], o);

    if (lane == 0) {
        float z[NE];
        float best = -1e30f; int bi = 0;
        #pragma unroll
        for (int j = 0; j < NE; j++) {
            float lg = acc[j] + rb3[j];
            z[j] = (lg + gumbel[(size_t)tok * NE + j]) / 0.07f;
            if (z[j] > best) { best = z[j]; bi = j; }
        }
        float ex[NE], sum = 0.f;
        #pragma unroll
        for (int j = 0; j < NE; j++) { ex[j] = expf(z[j] - best); sum += ex[j]; }
        #pragma unroll
        for (int j = 0; j < NE; j++) {
            float ys = ex[j] / sum;
            float hard = (j == bi) ? 1.f : 0.f;
            outRW[(size_t)tok * NE + j] = (hard + ys) - ys;
        }
        outIdx[tok] = (float)bi;
        int old = g_eidx[tok];
        if (bi != old) {
            atomicSub(&g_cnt[old], 1);
            atomicAdd(&g_cnt[bi], 1);
            g_eidx[tok] = bi;
        }
    }
}

__global__ void scan_kernel()
{
    if (threadIdx.x == 0 && blockIdx.x == 0) {
        int o = 0;
        for (int e = 0; e < NE; e++) { g_off[e] = o; g_cur[e] = o; o += g_cnt[e]; }
        g_off[NE] = o;
    }
}

__global__ void fill_perm()
{
    int t = blockIdx.x * blockDim.x + threadIdx.x;
    if (t < BT) {
        int e = g_eidx[t];
        int p = atomicAdd(&g_cur[e], 1);
        g_perm[p] = t;
    }
}

// ---------------- launch ----------------------------------------------------------
#define SM384 107520   // max(3*(448*80)=107520, 64*388*4=99328)
#define SM256 76800    // max(3*(320*80)=76800,  64*260*4=66560)
#define SM192 61440    // max(3*(256*80)=61440,  64*196*4=50176)

extern "C" void kernel_launch(void* const* d_in, const int* in_sizes, int n_in,
                              void* d_out, int out_size)
{
    const float* x      = (const float*)d_in[0];
    const float* gumbel = (const float*)d_in[1];
    const float* rw1  = (const float*)d_in[2];
    const float* rb1  = (const float*)d_in[3];
    const float* rg1  = (const float*)d_in[4];
    const float* rbe1 = (const float*)d_in[5];
    const float* rw2  = (const float*)d_in[6];
    const float* rb2  = (const float*)d_in[7];
    const float* rg2  = (const float*)d_in[8];
    const float* rbe2 = (const float*)d_in[9];
    const float* rw3  = (const float*)d_in[10];
    const float* rb3  = (const float*)d_in[11];
    const float* ew1  = (const float*)d_in[12];
    const float* eb1  = (const float*)d_in[13];
    const float* eg1  = (const float*)d_in[14];
    const float* ebe1 = (const float*)d_in[15];
    const float* ew2  = (const float*)d_in[16];
    const float* eb2  = (const float*)d_in[17];
    const float* eg2  = (const float*)d_in[18];
    const float* ebe2 = (const float*)d_in[19];
    const float* ew3  = (const float*)d_in[20];
    const float* eb3  = (const float*)d_in[21];
    const float* eg3  = (const float*)d_in[22];
    const float* ebe3 = (const float*)d_in[23];
    const float* wqkv = (const float*)d_in[24];
    const float* bqkv = (const float*)d_in[25];
    const float* wo   = (const float*)d_in[26];
    const float* bo   = (const float*)d_in[27];
    const float* ng   = (const float*)d_in[28];
    const float* nb   = (const float*)d_in[29];

    float* outMain = (float*)d_out;
    float* outRW   = outMain + (size_t)BT * DOUT;
    float* outIdx  = outRW   + (size_t)BT * NE;

    float *bufB, *Yb, *fA, *fB, *bc;
    __half *t16a, *t16b, *y16, *wch, *rw1h, *rw2h, *ew1h, *ew2h, *ew3h;
    int *off, *perm, *flag, *nseg; void *cntp, *nflagp;
    cudaGetSymbolAddress((void**)&bufB, g_bufB);
    cudaGetSymbolAddress((void**)&Yb,   g_Y);
    cudaGetSymbolAddress((void**)&fA,   g_fA);
    cudaGetSymbolAddress((void**)&fB,   g_fB);
    cudaGetSymbolAddress((void**)&bc,   g_bc);
    cudaGetSymbolAddress((void**)&t16a, g_t16a);
    cudaGetSymbolAddress((void**)&t16b, g_t16b);
    cudaGetSymbolAddress((void**)&y16,  g_y16);
    cudaGetSymbolAddress((void**)&wch,  g_wch);
    cudaGetSymbolAddress((void**)&rw1h, g_rw1h);
    cudaGetSymbolAddress((void**)&rw2h, g_rw2h);
    cudaGetSymbolAddress((void**)&ew1h, g_ew1h);
    cudaGetSymbolAddress((void**)&ew2h, g_ew2h);
    cudaGetSymbolAddress((void**)&ew3h, g_ew3h);
    cudaGetSymbolAddress((void**)&off,  g_off);
    cudaGetSymbolAddress((void**)&perm, g_perm);
    cudaGetSymbolAddress((void**)&flag, g_flag);
    cudaGetSymbolAddress((void**)&nseg, g_nseg);
    cudaGetSymbolAddress(&cntp,   g_cnt);
    cudaGetSymbolAddress(&nflagp, g_nflag);

    cudaFuncSetAttribute((const void*)gemm_f<384,1,8,0,1>, cudaFuncAttributeMaxDynamicSharedMemorySize, SM384);
    cudaFuncSetAttribute((const void*)gemm_f<384,1,8,0,0>, cudaFuncAttributeMaxDynamicSharedMemorySize, SM384);
    cudaFuncSetAttribute((const void*)gemm_f<192,2,4,1,0>, cudaFuncAttributeMaxDynamicSharedMemorySize, SM192);
    cudaFuncSetAttribute((const void*)gemm_f<256,2,4,2,0>, cudaFuncAttributeMaxDynamicSharedMemorySize, SM256);
    cudaFuncSetAttribute((const void*)gemm_f<256,2,4,3,0>, cudaFuncAttributeMaxDynamicSharedMemorySize, SM256);
    cudaFuncSetAttribute((const void*)gemm_split,          cudaFuncAttributeMaxDynamicSharedMemorySize, TSMEM);

    cudaMemsetAsync(cntp, 0, NE * sizeof(int));
    cudaMemsetAsync(nflagp, 0, sizeof(int));

    // one-time prep: all weight fp16 conversions in one kernel + fused wc
    cvt16_all<<<(CTOT + 255) / 256, 256>>>(rw1, rw1h, rw2, rw2h, ew1, ew1h,
                                           ew2, ew2h, ew3, ew3h);
    fuse_wo_wv<<<dim3(1, DOUT, NE), 256>>>(wqkv, bqkv, wo, bo, wch, bc);

    // ---- router (fused GEMM+LN; x converted in-loader) ----
    gemm_f<384,1,8,0,1><<<dim3(BT/64,1,1), 256, SM384>>>(
        x, nullptr, nullptr, rw1h, rb1, rg1, rbe1, nullptr, t16a, nullptr, nullptr,
        DIN, nullptr, 0, 0, 0, BT);
    gemm_f<192,2,4,1,0><<<dim3(BT/64,1,1), 256, SM192>>>(
        nullptr, t16a, nullptr, rw2h, rb2, rg2, rbe2, bufB, nullptr, nullptr, nullptr,
        DH, nullptr, 0, 0, 0, BT);
    routing_kernel<<<BT/8, 256>>>(bufB, rw3, rb3, gumbel, outRW, outIdx);
    set_nseg<<<1, 32>>>();

    // ---- exact recheck of flagged tokens (split-tf32 on RAW fp32) ----
    gemm_split<<<dim3(BT/128, DH/128, 1), 256, TSMEM>>>(
        x, flag, rw1, rb1, fA, DH, DIN, nseg, BT);
    ln_rows<<<BT/8, 256>>>(fA, fA, DH, rg1, rbe1, (const int*)nflagp);
    gemm_split<<<dim3(BT/128, 2, 1), 256, TSMEM>>>(
        fA, nullptr, rw2, rb2, fB, DH2, DH, nseg, BT);
    ln_rows<<<BT/8, 256>>>(fB, fB, DH2, rg2, rbe2, (const int*)nflagp);
    routing_fix<<<BT/8, 256>>>(fB, rw3, rb3, gumbel, outRW, outIdx);

    scan_kernel<<<1, 32>>>();
    fill_perm<<<BT/256, 256>>>();

    // ---- experts (compacted; fused GEMM+LN) ----
    gemm_f<384,1,8,0,1><<<dim3(BT/64,1,NE), 256, SM384>>>(
        x, nullptr, perm, ew1h, eb1, eg1, ebe1, nullptr, t16a, nullptr, nullptr,
        DIN, off, (long)DH * DIN, DH, DH, BT);
    gemm_f<384,1,8,0,0><<<dim3(BT/64,1,NE), 256, SM384>>>(
        nullptr, t16a, nullptr, ew2h, eb2, eg2, ebe2, nullptr, t16b, nullptr, nullptr,
        DH, off, (long)DH * DH, DH, DH, BT);
    gemm_f<256,2,4,2,0><<<dim3(BT/64,1,NE), 256, SM256>>>(
        nullptr, t16b, nullptr, ew3h, eb3, eg3, ebe3, Yb, y16, nullptr, nullptr,
        DH, off, (long)DOUT * DH, DOUT, DOUT, BT);
    // wc GEMM + residual + final LN + scatter (attention == V; wo@wv prefused)
    gemm_f<256,2,4,3,0><<<dim3(BT/64,1,NE), 256, SM256>>>(
        nullptr, y16, nullptr, wch, bc, ng, nb, outMain, nullptr, Yb, perm,
        DOUT, off, (long)DOUT * DOUT, DOUT, DOUT, BT);
}

// round 11
// speedup vs baseline: 1.0631x; 1.0631x over previous
#include <cuda_runtime.h>
#include <cuda_fp16.h>
#include <mma.h>
#include <math.h>
#include <stdint.h>

using namespace nvcuda;

// Problem constants
#define BT   32768
#define DIN  768
#define DH   384
#define DH2  192
#define DOUT 256
#define NE   5
#define DELTA 0.35f

// ---- tf32 split GEMM config (recheck path) ----
#define LDS_PAD 20
#define TSTAGE_FLOATS 5120
#define TSTAGE_BYTES  20480
#define TBOFF_BYTES   10240
#define TSMEM (4 * TSTAGE_BYTES)

// ---------------- scratch (device globals) ----------------
__device__ float  g_Y[(size_t)BT * DOUT];
__device__ float  g_fA[(size_t)BT * DH];
__device__ float  g_fB[(size_t)BT * DH2];
__device__ float  g_bc[NE * DOUT];
__device__ __half g_x16[(size_t)BT * DIN];
__device__ __half g_t16a[(size_t)BT * DH];
__device__ __half g_t16b[(size_t)BT * DH];
__device__ __half g_y16[(size_t)BT * DOUT];
__device__ __half g_wch[(size_t)NE * DOUT * DOUT];
__device__ __half g_rw1h[DH * DIN];
__device__ __half g_rw2h[DH2 * DH];
__device__ __half g_ew1h[(size_t)NE * DH * DIN];
__device__ __half g_ew2h[(size_t)NE * DH * DH];
__device__ __half g_ew3h[(size_t)NE * DOUT * DH];
__device__ int    g_eidx[BT];
__device__ int    g_perm[BT];
__device__ int    g_cnt[NE];
__device__ int    g_off[NE + 1];
__device__ int    g_cur[NE];
__device__ int    g_flag[BT];
__device__ int    g_nflag;
__device__ int    g_nseg[2];

__device__ __forceinline__ float tf32r(float x) { return wmma::__float_to_tf32(x); }

__device__ __forceinline__ uint32_t smem_u32(const void* p) {
    uint32_t a;
    asm("{ .reg .u64 t; cvta.to.shared.u64 t, %1; cvt.u32.u64 %0, t; }" : "=r"(a) : "l"(p));
    return a;
}
__device__ __forceinline__ void cpasync16(uint32_t dst, const void* src) {
    asm volatile("{ .reg .u64 g; cvta.to.global.u64 g, %1;"
                 "cp.async.ca.shared.global [%0], [g], 16; }"
                 :: "r"(dst), "l"(src) : "memory");
}
#define CP_COMMIT() asm volatile("cp.async.commit_group;" ::: "memory")
#define CP_WAIT1()  asm volatile("cp.async.wait_group 1;" ::: "memory")
#define CP_WAIT2()  asm volatile("cp.async.wait_group 2;" ::: "memory")
#define CP_WAIT0()  asm volatile("cp.async.wait_group 0;" ::: "memory")

// ============ fused fp16 GEMM + bias + LayerNorm epilogue (round-8 config) =======
// Block: BM=64 rows x BN=N cols (full row), 256 threads, 3-stage cp.async.
// MODE 0: LN+ReLU -> fp16    MODE 1: LN+ReLU -> fp32
// MODE 2: LN -> fp16+fp32    MODE 3: +Y residual, LN, scatter fp32 via perm
// MODE 4: LN+ReLU -> router head inline (logits+gumbel+softmax+argmax+flag)
// seg != nullptr => segmented (blockIdx.z = expert); gather maps A rows.
template<int BN, int WM, int WN, int MODE>
__global__ void __launch_bounds__(256, 1)
gemm_f(const __half* __restrict__ A, const int* __restrict__ gather,
       const __half* __restrict__ W, const float* __restrict__ bias,
       const float* __restrict__ lng, const float* __restrict__ lnb,
       float* __restrict__ out32, __half* __restrict__ out16,
       const float* __restrict__ addY, const int* __restrict__ permArr,
       int K, const int* __restrict__ seg, long wstride, int bstride,
       int lnstride, int Mtot,
       const float* __restrict__ rw3, const float* __restrict__ rb3,
       const float* __restrict__ gumb, float* __restrict__ outIdx)
{
    constexpr int CH = (64 + BN) / 64;     // 16B chunks per thread per stage
    constexpr int MF = 64 / WM / 16;
    constexpr int NF = BN / WN / 16;
    constexpr int STAGE_B = (64 + BN) * 80;
    constexpr int SLD = BN + 4;
    constexpr int NW = BN / 32;

    extern __shared__ char smraw[];

    int e = 0, rowbase = 0, segM = Mtot;
    if (seg) { e = blockIdx.z; rowbase = seg[e]; segM = seg[e + 1] - rowbase; }
    int mt = blockIdx.x * 64;
    if (mt >= segM) return;

    const __half* Wp = W + (long)e * wstride;
    const float*  bp = bias + (long)e * bstride;

    int tid  = threadIdx.x;
    int wid  = tid >> 5;
    int lane = tid & 31;
    int wm = (WM == 1) ? 0 : (wid / WN);
    int wn = (WM == 1) ? wid : (wid % WN);

    // loader: chunk 0 = A row (tid>>2); chunks 1..CH-1 = B rows
    int ra = tid >> 2;
    int c8 = (tid & 3) * 8;
    int mr = mt + ra; if (mr > segM - 1) mr = segM - 1;
    int ar = gather ? gather[rowbase + mr] : rowbase + mr;
    const __half* gp[CH];
    uint32_t so[CH];
    gp[0] = A + (size_t)ar * K + c8;
    so[0] = (uint32_t)(ra * 40 + c8) * 2;
    #pragma unroll
    for (int i = 1; i < CH; i++) {
        int rb = ra + (i - 1) * 64;
        gp[i] = Wp + (size_t)rb * K + c8;
        so[i] = (uint32_t)(5120 + (rb * 40 + c8) * 2);
    }

    uint32_t smb = smem_u32(smraw);
    int nk = K / 32;

    auto issue = [&](int stage, int kb) {
        uint32_t base = smb + (uint32_t)stage * STAGE_B;
        int k = kb * 32;
        #pragma unroll
        for (int i = 0; i < CH; i++)
            cpasync16(base + so[i], gp[i] + k);
    };

    wmma::fragment<wmma::accumulator, 16, 16, 16, float> acc[MF][NF];
    #pragma unroll
    for (int mi = 0; mi < MF; mi++)
        #pragma unroll
        for (int ni = 0; ni < NF; ni++) wmma::fill_fragment(acc[mi][ni], 0.f);

    issue(0, 0); CP_COMMIT();
    issue(1, 1); CP_COMMIT();

    for (int kb = 0; kb < nk; kb++) {
        CP_WAIT1();
        __syncthreads();
        const __half* sa = (const __half*)(smraw + (kb % 3) * STAGE_B);
        const __half* sb = sa + 2560;

        #pragma unroll
        for (int ks = 0; ks < 2; ks++) {
            wmma::fragment<wmma::matrix_a, 16, 16, 16, __half, wmma::row_major> a[MF];
            wmma::fragment<wmma::matrix_b, 16, 16, 16, __half, wmma::col_major> b[NF];
            #pragma unroll
            for (int mi = 0; mi < MF; mi++)
                wmma::load_matrix_sync(a[mi], sa + (wm * (64 / WM) + mi * 16) * 40 + ks * 16, 40);
            #pragma unroll
            for (int ni = 0; ni < NF; ni++)
                wmma::load_matrix_sync(b[ni], sb + (wn * (BN / WN) + ni * 16) * 40 + ks * 16, 40);
            #pragma unroll
            for (int mi = 0; mi < MF; mi++)
                #pragma unroll
                for (int ni = 0; ni < NF; ni++)
                    wmma::mma_sync(acc[mi][ni], a[mi], b[ni], acc[mi][ni]);
        }

        int nkb = kb + 2;
        if (nkb < nk) issue(nkb % 3, nkb);
        CP_COMMIT();
    }

    // ---- epilogue: stage full 64 x BN tile, bias + LN (+relu/residual), write ----
    CP_WAIT0();
    __syncthreads();
    float* stg = (float*)smraw;
    #pragma unroll
    for (int mi = 0; mi < MF; mi++)
        #pragma unroll
        for (int ni = 0; ni < NF; ni++)
            wmma::store_matrix_sync(stg + (wm * (64 / WM) + mi * 16) * SLD + wn * (BN / WN) + ni * 16,
                                    acc[mi][ni], SLD, wmma::mem_row_major);
    __syncthreads();

    const float* gpp = lng + (long)e * lnstride;
    const float* bpp = lnb + (long)e * lnstride;

    #pragma unroll
    for (int j = 0; j < 8; j++) {
        int r = wid * 8 + j;
        int m = mt + r;
        if (m >= segM) continue;   // r uniform per warp: no shuffle divergence
        const float* srow = stg + r * SLD;

        float v[NW];
        float s = 0.f;
        #pragma unroll
        for (int i = 0; i < NW; i++) {
            int c = lane + i * 32;
            float valf = srow[c] + bp[c];
            if (MODE == 3) valf += addY[(size_t)(rowbase + m) * BN + c];
            v[i] = valf; s += valf;
        }
        #pragma unroll
        for (int o = 16; o; o >>= 1) s += __shfl_xor_sync(0xffffffffu, s, o);
        float mu = s / (float)BN;
        float sq = 0.f;
        #pragma unroll
        for (int i = 0; i < NW; i++) { float d = v[i] - mu; sq += d * d; }
        #pragma unroll
        for (int o = 16; o; o >>= 1) sq += __shfl_xor_sync(0xffffffffu, sq, o);
        float inv = 1.0f / sqrtf(sq / (float)BN + 1e-5f);

        if (MODE == 4) {
            // LN+ReLU in registers, then router head inline (mirrors routing_kernel)
            int tok = rowbase + m;
            float hv[NW];
            #pragma unroll
            for (int i = 0; i < NW; i++) {
                int c = lane + i * 32;
                hv[i] = fmaxf((v[i] - mu) * inv * gpp[c] + bpp[c], 0.f);
            }
            float accj[NE];
            #pragma unroll
            for (int jj = 0; jj < NE; jj++) accj[jj] = 0.f;
            #pragma unroll
            for (int i = 0; i < NW; i++) {
                int c = lane + i * 32;
                #pragma unroll
                for (int jj = 0; jj < NE; jj++)
                    accj[jj] = fmaf(hv[i], rw3[jj * DH2 + c], accj[jj]);
            }
            #pragma unroll
            for (int jj = 0; jj < NE; jj++)
                #pragma unroll
                for (int o = 16; o; o >>= 1)
                    accj[jj] += __shfl_xor_sync(0xffffffffu, accj[jj], o);
            if (lane == 0) {
                float z[NE];
                float best = -1e30f, second = -1e30f; int bi = 0;
                #pragma unroll
                for (int jj = 0; jj < NE; jj++) {
                    float lg = accj[jj] + rb3[jj];
                    z[jj] = (lg + gumb[(size_t)tok * NE + jj]) / 0.07f;
                    if (z[jj] > best) { second = best; best = z[jj]; bi = jj; }
                    else if (z[jj] > second) second = z[jj];
                }
                float ex[NE], sum = 0.f;
                #pragma unroll
                for (int jj = 0; jj < NE; jj++) { ex[jj] = expf(z[jj] - best); sum += ex[jj]; }
                #pragma unroll
                for (int jj = 0; jj < NE; jj++) {
                    float ys = ex[jj] / sum;
                    float hard = (jj == bi) ? 1.f : 0.f;
                    out32[(size_t)tok * NE + jj] = (hard + ys) - ys;
                }
                outIdx[tok] = (float)bi;
                g_eidx[tok] = bi;
                atomicAdd(&g_cnt[bi], 1);
                if (best - second < DELTA) {
                    int p = atomicAdd(&g_nflag, 1);
                    g_flag[p] = tok;
                }
            }
        } else {
            size_t orow = (MODE == 3) ? (size_t)permArr[rowbase + m] : (size_t)(rowbase + m);
            #pragma unroll
            for (int i = 0; i < NW; i++) {
                int c = lane + i * 32;
                float o2 = (v[i] - mu) * inv * gpp[c] + bpp[c];
                if (MODE <= 1) o2 = fmaxf(o2, 0.f);
                if (MODE == 1 || MODE == 2 || MODE == 3) out32[orow * BN + c] = o2;
                if (MODE == 0 || MODE == 2) out16[orow * BN + c] = __float2half_rn(o2);
            }
        }
    }
}

// ============ split-tf32 GEMM (~2^-24) — exact recheck path only ==================
__global__ void __launch_bounds__(256, 1)
gemm_split(const float* __restrict__ A, const int* __restrict__ gather,
           const float* __restrict__ W, const float* __restrict__ bias,
           float* __restrict__ C, int N, int K,
           const int* __restrict__ seg, int Mtot)
{
    extern __shared__ float tsm[];

    int rowbase = 0, segM = Mtot;
    if (seg) { rowbase = seg[0]; segM = seg[1] - rowbase; }
    int mt = blockIdx.x * 128;
    if (mt >= segM) return;

    const float* bp = bias;
    int n0 = blockIdx.y * 128;

    int tid = threadIdx.x;
    int wid = tid >> 5;
    int wm  = wid >> 1;
    int wn  = wid & 1;

    int rA0 = tid >> 2,         cA0 = (tid & 3) * 4;
    int rA1 = (tid + 256) >> 2;
    int mr0 = mt + rA0; if (mr0 > segM - 1) mr0 = segM - 1;
    int mr1 = mt + rA1; if (mr1 > segM - 1) mr1 = segM - 1;
    int ar0 = gather ? gather[rowbase + mr0] : rowbase + mr0;
    int ar1 = gather ? gather[rowbase + mr1] : rowbase + mr1;
    const float* ap0 = A + (size_t)ar0 * K + cA0;
    const float* ap1 = A + (size_t)ar1 * K + cA0;
    int nr0 = n0 + rA0; if (nr0 > N - 1) nr0 = N - 1;
    int nr1 = n0 + rA1; if (nr1 > N - 1) nr1 = N - 1;
    const float* bpt0 = W + (size_t)nr0 * K + cA0;
    const float* bpt1 = W + (size_t)nr1 * K + cA0;

    uint32_t smb = smem_u32(tsm);
    uint32_t offA0 = (uint32_t)(rA0 * LDS_PAD + cA0) * 4;
    uint32_t offA1 = (uint32_t)(rA1 * LDS_PAD + cA0) * 4;

    int nk = K / 16;

    auto issue = [&](int stage, int kb) {
        int k = kb * 16;
        uint32_t base = smb + stage * TSTAGE_BYTES;
        cpasync16(base + offA0, ap0 + k);
        cpasync16(base + offA1, ap1 + k);
        cpasync16(base + TBOFF_BYTES + offA0, bpt0 + k);
        cpasync16(base + TBOFF_BYTES + offA1, bpt1 + k);
    };

    wmma::fragment<wmma::accumulator, 16, 16, 8, float> acc[2][4];
    #pragma unroll
    for (int mi = 0; mi < 2; mi++)
        #pragma unroll
        for (int ni = 0; ni < 4; ni++) wmma::fill_fragment(acc[mi][ni], 0.f);

    issue(0, 0); CP_COMMIT();
    issue(1, 1); CP_COMMIT();
    issue(2, 2); CP_COMMIT();

    for (int kb = 0; kb < nk; kb++) {
        CP_WAIT2();
        __syncthreads();
        int st = kb & 3;
        const float* sa = tsm + st * TSTAGE_FLOATS;
        const float* sb = sa + 2560;

        #pragma unroll
        for (int ks = 0; ks < 2; ks++) {
            wmma::fragment<wmma::matrix_a, 16, 16, 8, wmma::precision::tf32, wmma::row_major> a[2], ah[2];
            wmma::fragment<wmma::matrix_b, 16, 16, 8, wmma::precision::tf32, wmma::col_major> b[4], bh[4];
            #pragma unroll
            for (int mi = 0; mi < 2; mi++)
                wmma::load_matrix_sync(a[mi], sa + (wm * 32 + mi * 16) * LDS_PAD + ks * 8, LDS_PAD);
            #pragma unroll
            for (int ni = 0; ni < 4; ni++)
                wmma::load_matrix_sync(b[ni], sb + (wn * 64 + ni * 16) * LDS_PAD + ks * 8, LDS_PAD);
            #pragma unroll
            for (int mi = 0; mi < 2; mi++)
                #pragma unroll
                for (int i = 0; i < a[mi].num_elements; i++) {
                    float h = tf32r(a[mi].x[i]);
                    ah[mi].x[i] = h;
                    a[mi].x[i] = tf32r(a[mi].x[i] - h);
                }
            #pragma unroll
            for (int ni = 0; ni < 4; ni++)
                #pragma unroll
                for (int i = 0; i < b[ni].num_elements; i++) {
                    float h = tf32r(b[ni].x[i]);
                    bh[ni].x[i] = h;
                    b[ni].x[i] = tf32r(b[ni].x[i] - h);
                }
            #pragma unroll
            for (int mi = 0; mi < 2; mi++)
                #pragma unroll
                for (int ni = 0; ni < 4; ni++) {
                    wmma::mma_sync(acc[mi][ni], ah[mi], bh[ni], acc[mi][ni]);
                    wmma::mma_sync(acc[mi][ni], ah[mi], b[ni],  acc[mi][ni]);
                    wmma::mma_sync(acc[mi][ni], a[mi],  bh[ni], acc[mi][ni]);
                }
        }

        int nkb = kb + 3;
        if (nkb < nk) issue(nkb & 3, nkb);
        CP_COMMIT();
    }

    CP_WAIT0();
    __syncthreads();
    float* stage = tsm;
    const int SLD = 132;
    #pragma unroll
    for (int r = 0; r < 2; r++) {
        if ((wm >> 1) == r) {
            #pragma unroll
            for (int mi = 0; mi < 2; mi++)
                #pragma unroll
                for (int ni = 0; ni < 4; ni++)
                    wmma::store_matrix_sync(stage + ((wm & 1) * 32 + mi * 16) * SLD + wn * 64 + ni * 16,
                                            acc[mi][ni], SLD, wmma::mem_row_major);
        }
        __syncthreads();
        #pragma unroll
        for (int it = 0; it < 8; it++) {
            int fidx = tid + it * 256;
            int lrow = fidx >> 5;
            int c4 = (fidx & 31) * 4;
            int m = mt + r * 64 + lrow;
            int n = n0 + c4;
            if (m < segM && n < N) {
                float4 v = *(float4*)(stage + lrow * SLD + c4);
                float4 bv = *(const float4*)(bp + n);
                v.x += bv.x; v.y += bv.y; v.z += bv.z; v.w += bv.w;
                *(float4*)(C + (size_t)(rowbase + m) * N + n) = v;
            }
        }
        __syncthreads();
    }
}

// ---------------- fp32 -> fp16 conversion of x (vectorized) ----------------------
__global__ void cvt16(const float* __restrict__ src, __half* __restrict__ dst, int n4)
{
    int i = blockIdx.x * blockDim.x + threadIdx.x;
    if (i < n4) {
        float4 v = *(const float4*)(src + i * 4);
        *(__half2*)(dst + i * 4)     = __floats2half2_rn(v.x, v.y);
        *(__half2*)(dst + i * 4 + 2) = __floats2half2_rn(v.z, v.w);
    }
}

// ---------------- all weight fp32 -> fp16 conversions in ONE kernel ---------------
#define CN1 (DH * DIN / 4)
#define CN2 (DH2 * DH / 4)
#define CN3 (NE * DH * DIN / 4)
#define CN4 (NE * DH * DH / 4)
#define CN5 (NE * DOUT * DH / 4)
#define CTOT (CN1 + CN2 + CN3 + CN4 + CN5)

__global__ void cvt16_all(const float* s1, __half* d1, const float* s2, __half* d2,
                          const float* s3, __half* d3, const float* s4, __half* d4,
                          const float* s5, __half* d5)
{
    int i = blockIdx.x * blockDim.x + threadIdx.x;
    if (i >= CTOT) return;
    const float* s; __half* d; int o = i;
    if (o < CN1) { s = s1; d = d1; }
    else if ((o -= CN1) < CN2) { s = s2; d = d2; }
    else if ((o -= CN2) < CN3) { s = s3; d = d3; }
    else if ((o -= CN3) < CN4) { s = s4; d = d4; }
    else { o -= CN4; s = s5; d = d5; }
    float4 v = *(const float4*)(s + (size_t)o * 4);
    *(__half2*)(d + (size_t)o * 4)     = __floats2half2_rn(v.x, v.y);
    *(__half2*)(d + (size_t)o * 4 + 2) = __floats2half2_rn(v.z, v.w);
}

// ---------------- fuse wo @ wv (fp16 weights out) ---------------------------------
__global__ void fuse_wo_wv(const float* __restrict__ wqkv, const float* __restrict__ bqkv,
                           const float* __restrict__ wo, const float* __restrict__ bo,
                           __half* __restrict__ wch, float* __restrict__ bc)
{
    int e = blockIdx.z, n = blockIdx.y, k = threadIdx.x;
    const float* woR = wo + ((size_t)e * DOUT + n) * DOUT;
    const float* wv  = wqkv + (size_t)e * 3 * DOUT * DOUT + 2 * DOUT * DOUT;
    const float* bv  = bqkv + (size_t)e * 3 * DOUT + 2 * DOUT;
    float s = 0.f;
    for (int j = 0; j < DOUT; j++) s = fmaf(woR[j], wv[(size_t)j * DOUT + k], s);
    wch[((size_t)e * DOUT + n) * DOUT + k] = __float2half_rn(s);
    if (k == 0) {
        float sb = bo[e * DOUT + n];
        for (int j = 0; j < DOUT; j++) sb = fmaf(woR[j], bv[j], sb);
        bc[e * DOUT + n] = sb;
    }
}

// ---------------- row LayerNorm + ReLU, fp32 (recheck path only) -----------------
__global__ void ln_rows(const float* __restrict__ in, float* __restrict__ out, int Ncols,
                        const float* __restrict__ g, const float* __restrict__ b,
                        const int* __restrict__ Mdev)
{
    int row = blockIdx.x * 8 + (threadIdx.x >> 5);
    if (row >= *Mdev) return;
    int lane = threadIdx.x & 31;
    const float* ip = in + (size_t)row * Ncols;
    int nw = Ncols >> 5;

    float v[12];
    float s = 0.f;
    for (int i = 0; i < nw; i++) { v[i] = ip[lane + i * 32]; s += v[i]; }
    #pragma unroll
    for (int o = 16; o; o >>= 1) s += __shfl_xor_sync(0xffffffffu, s, o);
    float mu = s / (float)Ncols;
    float sq = 0.f;
    for (int i = 0; i < nw; i++) { float d = v[i] - mu; sq += d * d; }
    #pragma unroll
    for (int o = 16; o; o >>= 1) sq += __shfl_xor_sync(0xffffffffu, sq, o);
    float inv = 1.0f / sqrtf(sq / (float)Ncols + 1e-5f);

    float* op = out + (size_t)row * Ncols;
    for (int i = 0; i < nw; i++) {
        int c = lane + i * 32;
        op[c] = fmaxf((v[i] - mu) * inv * g[c] + b[c], 0.f);
    }
}

__global__ void set_nseg()
{
    if (threadIdx.x == 0) { g_nseg[0] = 0; g_nseg[1] = g_nflag; }
}

// ---------------- exact routing fix for flagged tokens ---------------------------
__global__ void routing_fix(const float* __restrict__ h2f, const float* __restrict__ rw3,
                            const float* __restrict__ rb3, const float* __restrict__ gumbel,
                            float* __restrict__ outRW, float* __restrict__ outIdx)
{
    int fi = blockIdx.x * 8 + (threadIdx.x >> 5);
    if (fi >= g_nflag) return;
    int lane = threadIdx.x & 31;
    int tok = g_flag[fi];
    const float* h = h2f + (size_t)fi * DH2;

    float acc[NE];
    #pragma unroll
    for (int j = 0; j < NE; j++) acc[j] = 0.f;
    #pragma unroll
    for (int i = 0; i < DH2 / 32; i++) {
        int k = lane + i * 32;
        float hv = h[k];
        #pragma unroll
        for (int j = 0; j < NE; j++)
            acc[j] = fmaf(hv, rw3[j * DH2 + k], acc[j]);
    }
    #pragma unroll
    for (int j = 0; j < NE; j++)
        #pragma unroll
        for (int o = 16; o; o >>= 1)
            acc[j] += __shfl_xor_sync(0xffffffffu, acc[j], o);

    if (lane == 0) {
        float z[NE];
        float best = -1e30f; int bi = 0;
        #pragma unroll
        for (int j = 0; j < NE; j++) {
            float lg = acc[j] + rb3[j];
            z[j] = (lg + gumbel[(size_t)tok * NE + j]) / 0.07f;
            if (z[j] > best) { best = z[j]; bi = j; }
        }
        float ex[NE], sum = 0.f;
        #pragma unroll
        for (int j = 0; j < NE; j++) { ex[j] = expf(z[j] - best); sum += ex[j]; }
        #pragma unroll
        for (int j = 0; j < NE; j++) {
            float ys = ex[j] / sum;
            float hard = (j == bi) ? 1.f : 0.f;
            outRW[(size_t)tok * NE + j] = (hard + ys) - ys;
        }
        outIdx[tok] = (float)bi;
        int old = g_eidx[tok];
        if (bi != old) {
            atomicSub(&g_cnt[old], 1);
            atomicAdd(&g_cnt[bi], 1);
            g_eidx[tok] = bi;
        }
    }
}

__global__ void scan_kernel()
{
    if (threadIdx.x == 0 && blockIdx.x == 0) {
        int o = 0;
        for (int e = 0; e < NE; e++) { g_off[e] = o; g_cur[e] = o; o += g_cnt[e]; }
        g_off[NE] = o;
    }
}

__global__ void fill_perm()
{
    int t = blockIdx.x * blockDim.x + threadIdx.x;
    if (t < BT) {
        int e = g_eidx[t];
        int p = atomicAdd(&g_cur[e], 1);
        g_perm[p] = t;
    }
}

// ---------------- launch ----------------------------------------------------------
#define SM384 107520   // max(3*(448*80)=107520, 64*388*4=99328)
#define SM256 76800    // max(3*(320*80)=76800,  64*260*4=66560)
#define SM192 61440    // max(3*(256*80)=61440,  64*196*4=50176)

extern "C" void kernel_launch(void* const* d_in, const int* in_sizes, int n_in,
                              void* d_out, int out_size)
{
    const float* x      = (const float*)d_in[0];
    const float* gumbel = (const float*)d_in[1];
    const float* rw1  = (const float*)d_in[2];
    const float* rb1  = (const float*)d_in[3];
    const float* rg1  = (const float*)d_in[4];
    const float* rbe1 = (const float*)d_in[5];
    const float* rw2  = (const float*)d_in[6];
    const float* rb2  = (const float*)d_in[7];
    const float* rg2  = (const float*)d_in[8];
    const float* rbe2 = (const float*)d_in[9];
    const float* rw3  = (const float*)d_in[10];
    const float* rb3  = (const float*)d_in[11];
    const float* ew1  = (const float*)d_in[12];
    const float* eb1  = (const float*)d_in[13];
    const float* eg1  = (const float*)d_in[14];
    const float* ebe1 = (const float*)d_in[15];
    const float* ew2  = (const float*)d_in[16];
    const float* eb2  = (const float*)d_in[17];
    const float* eg2  = (const float*)d_in[18];
    const float* ebe2 = (const float*)d_in[19];
    const float* ew3  = (const float*)d_in[20];
    const float* eb3  = (const float*)d_in[21];
    const float* eg3  = (const float*)d_in[22];
    const float* ebe3 = (const float*)d_in[23];
    const float* wqkv = (const float*)d_in[24];
    const float* bqkv = (const float*)d_in[25];
    const float* wo   = (const float*)d_in[26];
    const float* bo   = (const float*)d_in[27];
    const float* ng   = (const float*)d_in[28];
    const float* nb   = (const float*)d_in[29];

    float* outMain = (float*)d_out;
    float* outRW   = outMain + (size_t)BT * DOUT;
    float* outIdx  = outRW   + (size_t)BT * NE;

    float *Yb, *fA, *fB, *bc;
    __half *x16, *t16a, *t16b, *y16, *wch, *rw1h, *rw2h, *ew1h, *ew2h, *ew3h;
    int *off, *perm, *flag, *nseg; void *cntp, *nflagp;
    cudaGetSymbolAddress((void**)&Yb,   g_Y);
    cudaGetSymbolAddress((void**)&fA,   g_fA);
    cudaGetSymbolAddress((void**)&fB,   g_fB);
    cudaGetSymbolAddress((void**)&bc,   g_bc);
    cudaGetSymbolAddress((void**)&x16,  g_x16);
    cudaGetSymbolAddress((void**)&t16a, g_t16a);
    cudaGetSymbolAddress((void**)&t16b, g_t16b);
    cudaGetSymbolAddress((void**)&y16,  g_y16);
    cudaGetSymbolAddress((void**)&wch,  g_wch);
    cudaGetSymbolAddress((void**)&rw1h, g_rw1h);
    cudaGetSymbolAddress((void**)&rw2h, g_rw2h);
    cudaGetSymbolAddress((void**)&ew1h, g_ew1h);
    cudaGetSymbolAddress((void**)&ew2h, g_ew2h);
    cudaGetSymbolAddress((void**)&ew3h, g_ew3h);
    cudaGetSymbolAddress((void**)&off,  g_off);
    cudaGetSymbolAddress((void**)&perm, g_perm);
    cudaGetSymbolAddress((void**)&flag, g_flag);
    cudaGetSymbolAddress((void**)&nseg, g_nseg);
    cudaGetSymbolAddress(&cntp,   g_cnt);
    cudaGetSymbolAddress(&nflagp, g_nflag);

    cudaFuncSetAttribute((const void*)gemm_f<384,1,8,0>, cudaFuncAttributeMaxDynamicSharedMemorySize, SM384);
    cudaFuncSetAttribute((const void*)gemm_f<192,2,4,4>, cudaFuncAttributeMaxDynamicSharedMemorySize, SM192);
    cudaFuncSetAttribute((const void*)gemm_f<256,2,4,2>, cudaFuncAttributeMaxDynamicSharedMemorySize, SM256);
    cudaFuncSetAttribute((const void*)gemm_f<256,2,4,3>, cudaFuncAttributeMaxDynamicSharedMemorySize, SM256);
    cudaFuncSetAttribute((const void*)gemm_split,        cudaFuncAttributeMaxDynamicSharedMemorySize, TSMEM);

    cudaMemsetAsync(cntp, 0, NE * sizeof(int));
    cudaMemsetAsync(nflagp, 0, sizeof(int));

    // one-time prep: fp16 conversions (x + all weights merged) + fused wc
    cvt16<<<(BT * DIN / 4 + 255) / 256, 256>>>(x, x16, BT * DIN / 4);
    cvt16_all<<<(CTOT + 255) / 256, 256>>>(rw1, rw1h, rw2, rw2h, ew1, ew1h,
                                           ew2, ew2h, ew3, ew3h);
    fuse_wo_wv<<<dim3(1, DOUT, NE), 256>>>(wqkv, bqkv, wo, bo, wch, bc);

    // ---- router (fused GEMM+LN; router head fused into GEMM2 epilogue) ----
    gemm_f<384,1,8,0><<<dim3(BT/64,1,1), 256, SM384>>>(
        x16, nullptr, rw1h, rb1, rg1, rbe1, nullptr, t16a, nullptr, nullptr,
        DIN, nullptr, 0, 0, 0, BT, nullptr, nullptr, nullptr, nullptr);
    gemm_f<192,2,4,4><<<dim3(BT/64,1,1), 256, SM192>>>(
        t16a, nullptr, rw2h, rb2, rg2, rbe2, outRW, nullptr, nullptr, nullptr,
        DH, nullptr, 0, 0, 0, BT, rw3, rb3, gumbel, outIdx);
    set_nseg<<<1, 32>>>();

    // ---- exact recheck of flagged tokens (split-tf32 on RAW fp32) ----
    gemm_split<<<dim3(BT/128, DH/128, 1), 256, TSMEM>>>(
        x, flag, rw1, rb1, fA, DH, DIN, nseg, BT);
    ln_rows<<<BT/8, 256>>>(fA, fA, DH, rg1, rbe1, (const int*)nflagp);
    gemm_split<<<dim3(BT/128, 2, 1), 256, TSMEM>>>(
        fA, nullptr, rw2, rb2, fB, DH2, DH, nseg, BT);
    ln_rows<<<BT/8, 256>>>(fB, fB, DH2, rg2, rbe2, (const int*)nflagp);
    routing_fix<<<BT/8, 256>>>(fB, rw3, rb3, gumbel, outRW, outIdx);

    scan_kernel<<<1, 32>>>();
    fill_perm<<<BT/256, 256>>>();

    // ---- experts (compacted; fused GEMM+LN) ----
    gemm_f<384,1,8,0><<<dim3(BT/64,1,NE), 256, SM384>>>(
        x16, perm, ew1h, eb1, eg1, ebe1, nullptr, t16a, nullptr, nullptr,
        DIN, off, (long)DH * DIN, DH, DH, BT, nullptr, nullptr, nullptr, nullptr);
    gemm_f<384,1,8,0><<<dim3(BT/64,1,NE), 256, SM384>>>(
        t16a, nullptr, ew2h, eb2, eg2, ebe2, nullptr, t16b, nullptr, nullptr,
        DH, off, (long)DH * DH, DH, DH, BT, nullptr, nullptr, nullptr, nullptr);
    gemm_f<256,2,4,2><<<dim3(BT/64,1,NE), 256, SM256>>>(
        t16b, nullptr, ew3h, eb3, eg3, ebe3, Yb, y16, nullptr, nullptr,
        DH, off, (long)DOUT * DH, DOUT, DOUT, BT, nullptr, nullptr, nullptr, nullptr);
    // wc GEMM + residual + final LN + scatter (attention == V; wo@wv prefused)
    gemm_f<256,2,4,3><<<dim3(BT/64,1,NE), 256, SM256>>>(
        y16, nullptr, wch, bc, ng, nb, outMain, nullptr, Yb, perm,
        DOUT, off, (long)DOUT * DOUT, DOUT, DOUT, BT, nullptr, nullptr, nullptr, nullptr);
}